// round 13
// baseline (speedup 1.0000x reference)
#include <cuda_runtime.h>
#include <cuda_bf16.h>
#include <cstdint>
#include <cstddef>

// Shapes: B=64, S=512, D=768, H=512, T=37. Output: scalar f32 loss.

// ---------------- device scratch (no runtime allocation) ----------------
__device__ __align__(16) __nv_bfloat16 g_h[(size_t)32768 * 512];   // 32 MB hidden
__device__ __align__(16) float g_expem[(size_t)32768 * 37];        // exp(logits)
__device__ float g_partial[64];

typedef unsigned long long u64;

// ---------------- helpers ----------------
__device__ __forceinline__ void mma16816(float* d, const unsigned* a, const unsigned* b) {
    asm volatile(
        "mma.sync.aligned.m16n8k16.row.col.f32.bf16.bf16.f32 "
        "{%0,%1,%2,%3},{%4,%5,%6,%7},{%8,%9},{%0,%1,%2,%3};\n"
        : "+f"(d[0]), "+f"(d[1]), "+f"(d[2]), "+f"(d[3])
        : "r"(a[0]), "r"(a[1]), "r"(a[2]), "r"(a[3]), "r"(b[0]), "r"(b[1]));
}

__device__ __forceinline__ void ldsm_x4(unsigned& r0, unsigned& r1, unsigned& r2,
                                        unsigned& r3, uint32_t addr) {
    asm volatile("ldmatrix.sync.aligned.m8n8.x4.shared.b16 {%0,%1,%2,%3}, [%4];"
                 : "=r"(r0), "=r"(r1), "=r"(r2), "=r"(r3) : "r"(addr));
}

__device__ __forceinline__ uint32_t smem_u32(const void* p) {
    uint32_t a;
    asm("{ .reg .u64 t; cvta.to.shared.u64 t, %1; cvt.u32.u64 %0, t; }" : "=r"(a) : "l"(p));
    return a;
}

__device__ __forceinline__ uint2 pack_bf16x4(float a, float b, float c, float d) {
    __nv_bfloat162 h0 = __floats2bfloat162_rn(a, b);
    __nv_bfloat162 h1 = __floats2bfloat162_rn(c, d);
    uint2 r;
    r.x = *reinterpret_cast<unsigned*>(&h0);
    r.y = *reinterpret_cast<unsigned*>(&h1);
    return r;
}

__device__ __forceinline__ u64 pack2(float lo, float hi) {
    u64 v; asm("mov.b64 %0, {%1, %2};" : "=l"(v) : "f"(lo), "f"(hi)); return v;
}
__device__ __forceinline__ void unpack2(u64 v, float& lo, float& hi) {
    asm("mov.b64 {%0, %1}, %2;" : "=f"(lo), "=f"(hi) : "l"(v));
}
__device__ __forceinline__ u64 fma2(u64 a, u64 b, u64 c) {
    u64 d; asm("fma.rn.f32x2 %0, %1, %2, %3;" : "=l"(d) : "l"(a), "l"(b), "l"(c)); return d;
}
__device__ __forceinline__ u64 add2(u64 a, u64 b) {
    u64 d; asm("add.rn.f32x2 %0, %1, %2;" : "=l"(d) : "l"(a), "l"(b)); return d;
}

// ---------------- GEMM1: h = relu(X@W1 + b1), bf16 mma + LDSM ----------------
#define AS_STRIDE 776
#define BS_STRIDE 40
#define BS_TILE   (128 * BS_STRIDE)
#define G1_SMEM ((128 * AS_STRIDE + 2 * BS_TILE) * 2)
__global__ __launch_bounds__(256) void gemm1_kernel(const float* __restrict__ X,
                                                    const float* __restrict__ W1,
                                                    const float* __restrict__ b1,
                                                    int mtile0) {
    extern __shared__ __nv_bfloat16 smem[];
    __nv_bfloat16* As  = smem;                    // [128][776]
    __nv_bfloat16* Bsb = smem + 128 * AS_STRIDE;  // 2 x [128][40]
    const int tid  = threadIdx.x;
    const int lane = tid & 31;
    const int wid  = tid >> 5;
    const int wm   = wid & 3;
    const int wn   = wid >> 2;
    const int m0   = (mtile0 + blockIdx.x) * 128;
    const int wrow = wm * 32;
    const int wcol = wn * 64;
    const int gp   = lane >> 2;
    const int tg   = lane & 3;
    const int nc   = tid & 127;
    const int kgb  = (tid >> 7) * 4;

    const uint32_t as_u32 = smem_u32(As);
    const uint32_t bs_u32 = as_u32 + 128 * AS_STRIDE * 2;
    const int rowA  = wrow + (lane & 7) + ((lane >> 3) & 1) * 8;
    const int kaddA = ((lane >> 4) & 1) * 8;
    const uint32_t aoff = as_u32 + (uint32_t)(rowA * AS_STRIDE + kaddA) * 2;
    const int rowB  = wcol + (lane & 7) + ((lane >> 4) & 1) * 8;
    const int kaddB = ((lane >> 3) & 1) * 8;
    const uint32_t boff = (uint32_t)(rowB * BS_STRIDE + kaddB) * 2;

#pragma unroll 4
    for (int i = 0; i < 96; i++) {
        int idx = tid + i * 256;
        int r = idx / 192, c = idx % 192;
        float4 v = *(const float4*)(X + (size_t)(m0 + r) * 768 + c * 4);
        *(uint2*)&As[r * AS_STRIDE + c * 4] = pack_bf16x4(v.x, v.y, v.z, v.w);
    }
    __syncthreads();

    for (int nt = 0; nt < 4; nt++) {
        const int n0 = nt * 128;

        float acc[2][8][4];
#pragma unroll
        for (int i = 0; i < 2; i++)
#pragma unroll
            for (int j = 0; j < 8; j++)
#pragma unroll
                for (int k = 0; k < 4; k++) acc[i][j][k] = 0.f;

        float rb[4][4];
#pragma unroll
        for (int i = 0; i < 4; i++) {
            int kr = kgb + i * 8;
#pragma unroll
            for (int j = 0; j < 4; j++)
                rb[i][j] = W1[(size_t)(kr + j) * 512 + n0 + nc];
        }
#pragma unroll
        for (int i = 0; i < 4; i++) {
            int kr = kgb + i * 8;
            *(uint2*)&Bsb[nc * BS_STRIDE + kr] =
                pack_bf16x4(rb[i][0], rb[i][1], rb[i][2], rb[i][3]);
        }
#pragma unroll
        for (int i = 0; i < 4; i++) {
            int kr = 32 + kgb + i * 8;
#pragma unroll
            for (int j = 0; j < 4; j++)
                rb[i][j] = W1[(size_t)(kr + j) * 512 + n0 + nc];
        }
        __syncthreads();

        for (int kt = 0; kt < 24; kt++) {
            if (kt < 23) {
                __nv_bfloat16* Bw = Bsb + ((kt + 1) & 1) * BS_TILE;
#pragma unroll
                for (int i = 0; i < 4; i++) {
                    int kr = kgb + i * 8;
                    *(uint2*)&Bw[nc * BS_STRIDE + kr] =
                        pack_bf16x4(rb[i][0], rb[i][1], rb[i][2], rb[i][3]);
                }
            }
            if (kt < 22) {
                int k0 = (kt + 2) * 32;
#pragma unroll
                for (int i = 0; i < 4; i++) {
                    int kr = k0 + kgb + i * 8;
#pragma unroll
                    for (int j = 0; j < 4; j++)
                        rb[i][j] = W1[(size_t)(kr + j) * 512 + n0 + nc];
                }
            }
            const uint32_t bbase = bs_u32 + (uint32_t)((kt & 1) * BS_TILE * 2) + boff;
            const int kbase = kt * 32;
#pragma unroll
            for (int kk = 0; kk < 32; kk += 16) {
                const uint32_t ka2 = (uint32_t)(kbase + kk) * 2;
                unsigned af[2][4], bfr[8][2];
                ldsm_x4(af[0][0], af[0][1], af[0][2], af[0][3], aoff + ka2);
                ldsm_x4(af[1][0], af[1][1], af[1][2], af[1][3],
                        aoff + 16 * AS_STRIDE * 2 + ka2);
                const uint32_t bb = bbase + (uint32_t)kk * 2;
#pragma unroll
                for (int j2 = 0; j2 < 4; j2++)
                    ldsm_x4(bfr[2 * j2][0], bfr[2 * j2][1],
                            bfr[2 * j2 + 1][0], bfr[2 * j2 + 1][1],
                            bb + (uint32_t)(j2 * 16 * BS_STRIDE) * 2);
#pragma unroll
                for (int i = 0; i < 2; i++)
#pragma unroll
                    for (int j = 0; j < 8; j++) mma16816(acc[i][j], af[i], bfr[j]);
            }
            __syncthreads();
        }

#pragma unroll
        for (int i = 0; i < 2; i++) {
            int r0 = m0 + wrow + i * 16 + gp;
            int r1 = r0 + 8;
#pragma unroll
            for (int j = 0; j < 8; j++) {
                int c = n0 + wcol + j * 8 + tg * 2;
                float bia0 = b1[c], bia1 = b1[c + 1];
                float v00 = fmaxf(acc[i][j][0] + bia0, 0.f);
                float v01 = fmaxf(acc[i][j][1] + bia1, 0.f);
                float v10 = fmaxf(acc[i][j][2] + bia0, 0.f);
                float v11 = fmaxf(acc[i][j][3] + bia1, 0.f);
                __nv_bfloat162 o0 = __floats2bfloat162_rn(v00, v01);
                __nv_bfloat162 o1 = __floats2bfloat162_rn(v10, v11);
                *(__nv_bfloat162*)&g_h[(size_t)r0 * 512 + c] = o0;
                *(__nv_bfloat162*)&g_h[(size_t)r1 * 512 + c] = o1;
            }
        }
        __syncthreads();
    }
}

// ---------------- GEMM2: expem = exp(h@W2 + b2) ----------------
__global__ __launch_bounds__(128) void gemm2_kernel(const float* __restrict__ W2,
                                                    const float* __restrict__ b2,
                                                    int mtile0) {
    __shared__ __nv_bfloat16 As[128 * 72];
    __shared__ __nv_bfloat16 Bs[40 * 72];
    const int tid  = threadIdx.x;
    const int lane = tid & 31;
    const int wid  = tid >> 5;
    const int m0   = (mtile0 + blockIdx.x) * 128;
    const int wrow = wid * 32;
    const int gp   = lane >> 2;
    const int tg   = lane & 3;

    float acc[2][5][4];
#pragma unroll
    for (int i = 0; i < 2; i++)
#pragma unroll
        for (int j = 0; j < 5; j++)
#pragma unroll
            for (int k = 0; k < 4; k++) acc[i][j][k] = 0.f;

    for (int kt = 0; kt < 8; kt++) {
        __syncthreads();
        int k0 = kt * 64;
#pragma unroll
        for (int i = 0; i < 16; i++) {
            int idx = tid + i * 128;
            int r = idx >> 4, c = idx & 15;
            *(uint2*)&As[r * 72 + c * 4] =
                *(const uint2*)&g_h[(size_t)(m0 + r) * 512 + k0 + c * 4];
        }
        for (int idx = tid; idx < 40 * 64; idx += 128) {
            int k = idx & 63, n = idx >> 6;
            Bs[n * 72 + k] = (n < 37) ? __float2bfloat16(W2[(size_t)(k0 + k) * 37 + n])
                                      : __float2bfloat16(0.f);
        }
        __syncthreads();
#pragma unroll
        for (int kk = 0; kk < 64; kk += 16) {
            unsigned af[2][4], bfr[5][2];
#pragma unroll
            for (int i = 0; i < 2; i++) {
                int r = wrow + i * 16 + gp;
                af[i][0] = *(const unsigned*)&As[r * 72 + kk + tg * 2];
                af[i][1] = *(const unsigned*)&As[(r + 8) * 72 + kk + tg * 2];
                af[i][2] = *(const unsigned*)&As[r * 72 + kk + tg * 2 + 8];
                af[i][3] = *(const unsigned*)&As[(r + 8) * 72 + kk + tg * 2 + 8];
            }
#pragma unroll
            for (int j = 0; j < 5; j++) {
                int n = j * 8 + gp;
                bfr[j][0] = *(const unsigned*)&Bs[n * 72 + kk + tg * 2];
                bfr[j][1] = *(const unsigned*)&Bs[n * 72 + kk + tg * 2 + 8];
            }
#pragma unroll
            for (int i = 0; i < 2; i++)
#pragma unroll
                for (int j = 0; j < 5; j++) mma16816(acc[i][j], af[i], bfr[j]);
        }
    }

#pragma unroll
    for (int i = 0; i < 2; i++) {
        int r0 = m0 + wrow + i * 16 + gp;
        int r1 = r0 + 8;
#pragma unroll
        for (int j = 0; j < 5; j++) {
            int c = j * 8 + tg * 2;
            if (c < 37) {
                float bia = b2[c];
                g_expem[(size_t)r0 * 37 + c] = expf(acc[i][j][0] + bia);
                g_expem[(size_t)r1 * 37 + c] = expf(acc[i][j][2] + bia);
            }
            if (c + 1 < 37) {
                float bia = b2[c + 1];
                g_expem[(size_t)r0 * 37 + c + 1] = expf(acc[i][j][1] + bia);
                g_expem[(size_t)r1 * 37 + c + 1] = expf(acc[i][j][3] + bia);
            }
        }
    }
}

// ---------------- CRF: forward/backward split, LDS.128 quad step ----------------
// EP arrays padded to 20 pairs (indices 37..39 structurally zero). Alpha
// buffers 64-wide; cols 37..63 stay zero. Per step: 10 LDS.128 (ulonglong2)
// + 40 fma2 + 1 syncwarp.
struct QStep {
    u64 EPL[20], EPH[20];
};

__device__ __forceinline__ void quad_step(const float* __restrict__ buf,
                                          const QStep& q, float emL, float emH,
                                          float& naL, float& naH) {
    u64 L0 = 0ull, L1 = 0ull, H0 = 0ull, H1 = 0ull;
#pragma unroll
    for (int j = 0; j < 10; j++) {
        ulonglong2 v = *(const ulonglong2*)&buf[4 * j];   // LDS.128
        L0 = fma2(v.x, q.EPL[2 * j], L0);
        L1 = fma2(v.y, q.EPL[2 * j + 1], L1);
        H0 = fma2(v.x, q.EPH[2 * j], H0);
        H1 = fma2(v.y, q.EPH[2 * j + 1], H1);
    }
    float l0, l1, h0, h1;
    unpack2(add2(L0, L1), l0, l1);
    unpack2(add2(H0, H1), h0, h1);
    naL = (l0 + l1) * emL;
    naH = (h0 + h1) * emH;
}

__global__ __launch_bounds__(96) void crf_kernel(const float* __restrict__ trans,
                                                 const float* __restrict__ startt,
                                                 const float* __restrict__ endt,
                                                 const int* __restrict__ labels,
                                                 const void* __restrict__ mask,
                                                 int b0) {
    __shared__ __align__(16) float sa[2][64];
    __shared__ __align__(16) float sb[2][64];
    __shared__ float gp_s, lsB_s;
    const int b = b0 + blockIdx.x, tid = threadIdx.x;
    const int lane = tid & 31;
    const int wid  = tid >> 5;
    const unsigned FULL = 0xffffffffu;
    const size_t base = (size_t)b * 512;
    const int* lab = labels + base;

    int cnt = 0;
    const unsigned w0 = *(const unsigned*)mask;
    if (w0 == 0x01010101u) {
        const uint4* p = (const uint4*)((const unsigned char*)mask + base);
        uint4 v = p[lane];
        cnt = __popc(v.x & 0x01010101u) + __popc(v.y & 0x01010101u) +
              __popc(v.z & 0x01010101u) + __popc(v.w & 0x01010101u);
    } else if (w0 == 0x3F800000u) {
        const float* p = (const float*)mask + base;
        for (int i = lane; i < 512; i += 32) cnt += (p[i] != 0.f);
    } else {
        const int* p = (const int*)mask + base;
        for (int i = lane; i < 512; i += 32) cnt += (p[i] != 0);
    }
#pragma unroll
    for (int off = 16; off; off >>= 1) cnt += __shfl_xor_sync(FULL, cnt, off);
    const int len = cnt;
    const int mid = len >> 1;

    float logscaleF = 0.f;

    if (wid == 2) {
        float g = 0.f;
        for (int s = lane; s < len; s += 32)
            g += logf(g_expem[(base + s) * 37 + lab[s]]);
        for (int s = 1 + lane; s < len; s += 32)
            g += trans[lab[s - 1] * 37 + lab[s]];
        if (lane == 0) g += startt[lab[0]] + endt[lab[len - 1]];
#pragma unroll
        for (int off = 16; off; off >>= 1) g += __shfl_xor_sync(FULL, g, off);
        if (lane == 0) gp_s = g;
    } else if (wid == 0) {
        // ---- forward alpha: steps 1..mid; uses E columns ----
        const int t = lane;
        const bool hi = (t < 5);
        QStep q;
#pragma unroll 1
        for (int i = 0; i < 20; i++) {
            int i0 = 2 * i, i1 = 2 * i + 1;
            float eL0 = (i0 < 37) ? expf(trans[i0 * 37 + t]) : 0.f;
            float eL1 = (i1 < 37) ? expf(trans[i1 * 37 + t]) : 0.f;
            q.EPL[i] = pack2(eL0, eL1);
            float eH0 = (hi && i0 < 37) ? expf(trans[i0 * 37 + t + 32]) : 0.f;
            float eH1 = (hi && i1 < 37) ? expf(trans[i1 * 37 + t + 32]) : 0.f;
            q.EPH[i] = pack2(eH0, eH1);
        }
        const float* empL = g_expem + base * 37 + t;
        const float* empH = g_expem + base * 37 + (hi ? t + 32 : 36);

        sa[0][t] = expf(startt[t]) * empL[0];
        sa[0][t + 32] = (hi ? expf(startt[t + 32]) : 0.f) * empH[0];
        sa[1][t + 32] = 0.f;
        __syncwarp();

        float curL[8], nxtL[8], curH[8], nxtH[8];
#pragma unroll
        for (int u = 0; u < 8; u++) {
            curL[u] = empL[(1 + u) * 37];
            nxtL[u] = empL[(9 + u) * 37];
            curH[u] = empH[(1 + u) * 37];
            nxtH[u] = empH[(9 + u) * 37];
        }

        const int Gf = mid >> 3;
        float naL = 0.f, naH = 0.f;
        int s = 1;
#pragma unroll 1
        for (int g = 0; g < Gf; g++) {
#pragma unroll
            for (int u = 0; u < 8; u++) {
                const float* buf = sa[u & 1];
                quad_step(buf, q, curL[u], curH[u], naL, naH);
                if (u == 7) {
                    float scale = buf[0];
                    logscaleF += logf(scale);
                    float inv = 1.f / scale;
                    naL *= inv; naH *= inv;
                }
                float* wb = sa[(u + 1) & 1];
                wb[t] = naL;
                wb[t + 32] = naH;
                __syncwarp();
            }
            int sbase = s + 16;
#pragma unroll
            for (int u = 0; u < 8; u++) {
                curL[u] = nxtL[u]; curH[u] = nxtH[u];
                int ss = sbase + u; ss = (ss < 512) ? ss : 511;
                nxtL[u] = empL[ss * 37]; nxtH[u] = empH[ss * 37];
            }
            s += 8;
        }
#pragma unroll 1
        for (int u = 0; s <= mid; s++, u++) {
            const float* buf = sa[(s - 1) & 1];
            quad_step(buf, q, curL[u], curH[u], naL, naH);
            float* wb = sa[s & 1];
            wb[t] = naL;
            wb[t + 32] = naH;
            __syncwarp();
        }
    } else {
        // ---- backward g = em*beta: uses E rows ----
        const int t = lane;
        const bool hi = (t < 5);
        QStep q;
#pragma unroll 1
        for (int i = 0; i < 20; i++) {
            int i0 = 2 * i, i1 = 2 * i + 1;
            float eL0 = (i0 < 37) ? expf(trans[t * 37 + i0]) : 0.f;
            float eL1 = (i1 < 37) ? expf(trans[t * 37 + i1]) : 0.f;
            q.EPL[i] = pack2(eL0, eL1);
            float eH0 = (hi && i0 < 37) ? expf(trans[(t + 32) * 37 + i0]) : 0.f;
            float eH1 = (hi && i1 < 37) ? expf(trans[(t + 32) * 37 + i1]) : 0.f;
            q.EPH[i] = pack2(eH0, eH1);
        }
        const float* empL = g_expem + base * 37 + t;
        const float* empH = g_expem + base * 37 + (hi ? t + 32 : 36);

        sb[0][t] = empL[(size_t)(len - 1) * 37] * expf(endt[t]);
        sb[0][t + 32] = hi ? empH[(size_t)(len - 1) * 37] * expf(endt[t + 32]) : 0.f;
        sb[1][t + 32] = 0.f;
        __syncwarp();

        float curL[8], nxtL[8], curH[8], nxtH[8];
#pragma unroll
        for (int u = 0; u < 8; u++) {
            curL[u] = empL[(len - 2 - u) * 37];
            nxtL[u] = empL[(len - 10 - u) * 37];
            curH[u] = empH[(len - 2 - u) * 37];
            nxtH[u] = empH[(len - 10 - u) * 37];
        }

        const int V = len - 1 - mid;
        const int Gb = V >> 3;
        float naL = 0.f, naH = 0.f;
        float logscaleB = 0.f;
        int nb = len - 18;
        int v = 0;
#pragma unroll 1
        for (int g = 0; g < Gb; g++) {
#pragma unroll
            for (int u = 0; u < 8; u++) {
                const float* buf = sb[u & 1];
                quad_step(buf, q, curL[u], curH[u], naL, naH);
                if (u == 7) {
                    float scale = buf[0];
                    logscaleB += logf(scale);
                    float inv = 1.f / scale;
                    naL *= inv; naH *= inv;
                }
                float* wb = sb[(u + 1) & 1];
                wb[t] = naL;
                wb[t + 32] = naH;
                __syncwarp();
            }
#pragma unroll
            for (int u = 0; u < 8; u++) {
                curL[u] = nxtL[u]; curH[u] = nxtH[u];
                int ss = nb - u; ss = (ss > 0) ? ss : 0;
                nxtL[u] = empL[ss * 37]; nxtH[u] = empH[ss * 37];
            }
            nb -= 8;
            v += 8;
        }
#pragma unroll 1
        for (int u = 0; v < V; v++, u++) {
            const float* buf = sb[v & 1];
            quad_step(buf, q, curL[u], curH[u], naL, naH);
            float* wb = sb[(v + 1) & 1];
            wb[t] = naL;
            wb[t + 32] = naH;
            __syncwarp();
        }
        if (lane == 0) lsB_s = logscaleB;
    }
    __syncthreads();

    if (wid == 0) {
        const int t = lane;
        const bool hi = (t < 5);
        const int V = len - 1 - mid;
        const float* am = sa[mid & 1];
        const float* gm = sb[V & 1];
        float emLm = g_expem[(base + mid) * 37 + t];
        float emHm = hi ? g_expem[(base + mid) * 37 + t + 32] : 1.f;
        float z = am[t] * gm[t] / emLm + (hi ? am[t + 32] * gm[t + 32] / emHm : 0.f);
#pragma unroll
        for (int off = 16; off; off >>= 1) z += __shfl_xor_sync(FULL, z, off);
        if (t == 0) g_partial[b] = logscaleF + lsB_s + logf(z) - gp_s;
    }
}

// ---------------- finalize: mean over batches ----------------
__global__ void finalize_kernel(float* __restrict__ out) {
    const int t = threadIdx.x;
    float v = g_partial[t] + g_partial[t + 32];
#pragma unroll
    for (int off = 16; off; off >>= 1) v += __shfl_xor_sync(0xffffffffu, v, off);
    if (t == 0) out[0] = v * (1.f / 64.f);
}

// ---------------- launch: wave-aligned 2-chunk pipeline ----------------
// chunk0 = 148 m-tiles (batches 0..36) -> fills all 148 SMs exactly.
// chunk1 = 108 m-tiles (batches 37..63) -> 40 SMs left for overlapped
// gemm2(c0)+crf(c0) on stream s1.
extern "C" void kernel_launch(void* const* d_in, const int* in_sizes, int n_in,
                              void* d_out, int out_size) {
    const float* X      = (const float*)d_in[0];
    const void*  mask   = d_in[1];
    const int*   labels = (const int*)d_in[2];
    const float* W1     = (const float*)d_in[3];
    const float* b1     = (const float*)d_in[4];
    const float* W2     = (const float*)d_in[5];
    const float* b2     = (const float*)d_in[6];
    const float* trans  = (const float*)d_in[7];
    const float* startt = (const float*)d_in[8];
    const float* endt   = (const float*)d_in[9];
    float* out = (float*)d_out;

    static cudaStream_t s1 = nullptr;
    static cudaEvent_t evA = nullptr, evB = nullptr;
    if (!s1) {
        cudaFuncSetAttribute(gemm1_kernel,
                             cudaFuncAttributeMaxDynamicSharedMemorySize, G1_SMEM);
        cudaStreamCreateWithFlags(&s1, cudaStreamNonBlocking);
        cudaEventCreateWithFlags(&evA, cudaEventDisableTiming);
        cudaEventCreateWithFlags(&evB, cudaEventDisableTiming);
    }

    gemm1_kernel<<<148, 256, G1_SMEM>>>(X, W1, b1, 0);
    cudaEventRecord(evA, 0);
    gemm1_kernel<<<108, 256, G1_SMEM>>>(X, W1, b1, 148);   // default stream

    cudaStreamWaitEvent(s1, evA, 0);
    gemm2_kernel<<<148, 128, 0, s1>>>(W2, b2, 0);
    crf_kernel<<<37, 96, 0, s1>>>(trans, startt, endt, labels, mask, 0);
    cudaEventRecord(evB, s1);

    gemm2_kernel<<<108, 128>>>(W2, b2, 148);
    crf_kernel<<<27, 96>>>(trans, startt, endt, labels, mask, 37);
    cudaStreamWaitEvent(0, evB, 0);
    finalize_kernel<<<1, 32>>>(out);
}

// round 14
// speedup vs baseline: 1.0208x; 1.0208x over previous
#include <cuda_runtime.h>
#include <cuda_bf16.h>
#include <cstdint>
#include <cstddef>

// Shapes: B=64, S=512, D=768, H=512, T=37. Output: scalar f32 loss.

// ---------------- device scratch (no runtime allocation) ----------------
__device__ __align__(16) __nv_bfloat16 g_h[(size_t)32768 * 512];   // 32 MB hidden
__device__ __align__(16) float g_expem[(size_t)32768 * 37];        // exp(logits)
__device__ float g_partial[64];

typedef unsigned long long u64;

// ---------------- helpers ----------------
__device__ __forceinline__ void mma16816(float* d, const unsigned* a, const unsigned* b) {
    asm volatile(
        "mma.sync.aligned.m16n8k16.row.col.f32.bf16.bf16.f32 "
        "{%0,%1,%2,%3},{%4,%5,%6,%7},{%8,%9},{%0,%1,%2,%3};\n"
        : "+f"(d[0]), "+f"(d[1]), "+f"(d[2]), "+f"(d[3])
        : "r"(a[0]), "r"(a[1]), "r"(a[2]), "r"(a[3]), "r"(b[0]), "r"(b[1]));
}

__device__ __forceinline__ void ldsm_x4(unsigned& r0, unsigned& r1, unsigned& r2,
                                        unsigned& r3, uint32_t addr) {
    asm volatile("ldmatrix.sync.aligned.m8n8.x4.shared.b16 {%0,%1,%2,%3}, [%4];"
                 : "=r"(r0), "=r"(r1), "=r"(r2), "=r"(r3) : "r"(addr));
}

__device__ __forceinline__ uint32_t smem_u32(const void* p) {
    uint32_t a;
    asm("{ .reg .u64 t; cvta.to.shared.u64 t, %1; cvt.u32.u64 %0, t; }" : "=r"(a) : "l"(p));
    return a;
}

__device__ __forceinline__ uint2 pack_bf16x4(float a, float b, float c, float d) {
    __nv_bfloat162 h0 = __floats2bfloat162_rn(a, b);
    __nv_bfloat162 h1 = __floats2bfloat162_rn(c, d);
    uint2 r;
    r.x = *reinterpret_cast<unsigned*>(&h0);
    r.y = *reinterpret_cast<unsigned*>(&h1);
    return r;
}

__device__ __forceinline__ u64 pack2(float lo, float hi) {
    u64 v; asm("mov.b64 %0, {%1, %2};" : "=l"(v) : "f"(lo), "f"(hi)); return v;
}
__device__ __forceinline__ void unpack2(u64 v, float& lo, float& hi) {
    asm("mov.b64 {%0, %1}, %2;" : "=f"(lo), "=f"(hi) : "l"(v));
}
__device__ __forceinline__ u64 fma2(u64 a, u64 b, u64 c) {
    u64 d; asm("fma.rn.f32x2 %0, %1, %2, %3;" : "=l"(d) : "l"(a), "l"(b), "l"(c)); return d;
}
__device__ __forceinline__ u64 add2(u64 a, u64 b) {
    u64 d; asm("add.rn.f32x2 %0, %1, %2;" : "=l"(d) : "l"(a), "l"(b)); return d;
}
#define BAR_SYNC(id, cnt) \
    asm volatile("bar.sync %0, %1;" :: "r"(id), "r"(cnt) : "memory")

// ---------------- GEMM1: h = relu(X@W1 + b1), bf16 mma + LDSM ----------------
#define AS_STRIDE 776
#define BS_STRIDE 40
#define BS_TILE   (128 * BS_STRIDE)
#define G1_SMEM ((128 * AS_STRIDE + 2 * BS_TILE) * 2)
__global__ __launch_bounds__(256) void gemm1_kernel(const float* __restrict__ X,
                                                    const float* __restrict__ W1,
                                                    const float* __restrict__ b1,
                                                    int mtile0) {
    extern __shared__ __nv_bfloat16 smem[];
    __nv_bfloat16* As  = smem;                    // [128][776]
    __nv_bfloat16* Bsb = smem + 128 * AS_STRIDE;  // 2 x [128][40]
    const int tid  = threadIdx.x;
    const int lane = tid & 31;
    const int wid  = tid >> 5;
    const int wm   = wid & 3;
    const int wn   = wid >> 2;
    const int m0   = (mtile0 + blockIdx.x) * 128;
    const int wrow = wm * 32;
    const int wcol = wn * 64;
    const int gp   = lane >> 2;
    const int tg   = lane & 3;
    const int nc   = tid & 127;
    const int kgb  = (tid >> 7) * 4;

    const uint32_t as_u32 = smem_u32(As);
    const uint32_t bs_u32 = as_u32 + 128 * AS_STRIDE * 2;
    const int rowA  = wrow + (lane & 7) + ((lane >> 3) & 1) * 8;
    const int kaddA = ((lane >> 4) & 1) * 8;
    const uint32_t aoff = as_u32 + (uint32_t)(rowA * AS_STRIDE + kaddA) * 2;
    const int rowB  = wcol + (lane & 7) + ((lane >> 4) & 1) * 8;
    const int kaddB = ((lane >> 3) & 1) * 8;
    const uint32_t boff = (uint32_t)(rowB * BS_STRIDE + kaddB) * 2;

#pragma unroll 4
    for (int i = 0; i < 96; i++) {
        int idx = tid + i * 256;
        int r = idx / 192, c = idx % 192;
        float4 v = *(const float4*)(X + (size_t)(m0 + r) * 768 + c * 4);
        *(uint2*)&As[r * AS_STRIDE + c * 4] = pack_bf16x4(v.x, v.y, v.z, v.w);
    }
    __syncthreads();

    for (int nt = 0; nt < 4; nt++) {
        const int n0 = nt * 128;

        float acc[2][8][4];
#pragma unroll
        for (int i = 0; i < 2; i++)
#pragma unroll
            for (int j = 0; j < 8; j++)
#pragma unroll
                for (int k = 0; k < 4; k++) acc[i][j][k] = 0.f;

        float rb[4][4];
#pragma unroll
        for (int i = 0; i < 4; i++) {
            int kr = kgb + i * 8;
#pragma unroll
            for (int j = 0; j < 4; j++)
                rb[i][j] = W1[(size_t)(kr + j) * 512 + n0 + nc];
        }
#pragma unroll
        for (int i = 0; i < 4; i++) {
            int kr = kgb + i * 8;
            *(uint2*)&Bsb[nc * BS_STRIDE + kr] =
                pack_bf16x4(rb[i][0], rb[i][1], rb[i][2], rb[i][3]);
        }
#pragma unroll
        for (int i = 0; i < 4; i++) {
            int kr = 32 + kgb + i * 8;
#pragma unroll
            for (int j = 0; j < 4; j++)
                rb[i][j] = W1[(size_t)(kr + j) * 512 + n0 + nc];
        }
        __syncthreads();

        for (int kt = 0; kt < 24; kt++) {
            if (kt < 23) {
                __nv_bfloat16* Bw = Bsb + ((kt + 1) & 1) * BS_TILE;
#pragma unroll
                for (int i = 0; i < 4; i++) {
                    int kr = kgb + i * 8;
                    *(uint2*)&Bw[nc * BS_STRIDE + kr] =
                        pack_bf16x4(rb[i][0], rb[i][1], rb[i][2], rb[i][3]);
                }
            }
            if (kt < 22) {
                int k0 = (kt + 2) * 32;
#pragma unroll
                for (int i = 0; i < 4; i++) {
                    int kr = k0 + kgb + i * 8;
#pragma unroll
                    for (int j = 0; j < 4; j++)
                        rb[i][j] = W1[(size_t)(kr + j) * 512 + n0 + nc];
                }
            }
            const uint32_t bbase = bs_u32 + (uint32_t)((kt & 1) * BS_TILE * 2) + boff;
            const int kbase = kt * 32;
#pragma unroll
            for (int kk = 0; kk < 32; kk += 16) {
                const uint32_t ka2 = (uint32_t)(kbase + kk) * 2;
                unsigned af[2][4], bfr[8][2];
                ldsm_x4(af[0][0], af[0][1], af[0][2], af[0][3], aoff + ka2);
                ldsm_x4(af[1][0], af[1][1], af[1][2], af[1][3],
                        aoff + 16 * AS_STRIDE * 2 + ka2);
                const uint32_t bb = bbase + (uint32_t)kk * 2;
#pragma unroll
                for (int j2 = 0; j2 < 4; j2++)
                    ldsm_x4(bfr[2 * j2][0], bfr[2 * j2][1],
                            bfr[2 * j2 + 1][0], bfr[2 * j2 + 1][1],
                            bb + (uint32_t)(j2 * 16 * BS_STRIDE) * 2);
#pragma unroll
                for (int i = 0; i < 2; i++)
#pragma unroll
                    for (int j = 0; j < 8; j++) mma16816(acc[i][j], af[i], bfr[j]);
            }
            __syncthreads();
        }

#pragma unroll
        for (int i = 0; i < 2; i++) {
            int r0 = m0 + wrow + i * 16 + gp;
            int r1 = r0 + 8;
#pragma unroll
            for (int j = 0; j < 8; j++) {
                int c = n0 + wcol + j * 8 + tg * 2;
                float bia0 = b1[c], bia1 = b1[c + 1];
                float v00 = fmaxf(acc[i][j][0] + bia0, 0.f);
                float v01 = fmaxf(acc[i][j][1] + bia1, 0.f);
                float v10 = fmaxf(acc[i][j][2] + bia0, 0.f);
                float v11 = fmaxf(acc[i][j][3] + bia1, 0.f);
                __nv_bfloat162 o0 = __floats2bfloat162_rn(v00, v01);
                __nv_bfloat162 o1 = __floats2bfloat162_rn(v10, v11);
                *(__nv_bfloat162*)&g_h[(size_t)r0 * 512 + c] = o0;
                *(__nv_bfloat162*)&g_h[(size_t)r1 * 512 + c] = o1;
            }
        }
        __syncthreads();
    }
}

// ---------------- GEMM2: expem = exp(h@W2 + b2) ----------------
__global__ __launch_bounds__(128) void gemm2_kernel(const float* __restrict__ W2,
                                                    const float* __restrict__ b2,
                                                    int mtile0) {
    __shared__ __nv_bfloat16 As[128 * 72];
    __shared__ __nv_bfloat16 Bs[40 * 72];
    const int tid  = threadIdx.x;
    const int lane = tid & 31;
    const int wid  = tid >> 5;
    const int m0   = (mtile0 + blockIdx.x) * 128;
    const int wrow = wid * 32;
    const int gp   = lane >> 2;
    const int tg   = lane & 3;

    float acc[2][5][4];
#pragma unroll
    for (int i = 0; i < 2; i++)
#pragma unroll
        for (int j = 0; j < 5; j++)
#pragma unroll
            for (int k = 0; k < 4; k++) acc[i][j][k] = 0.f;

    for (int kt = 0; kt < 8; kt++) {
        __syncthreads();
        int k0 = kt * 64;
#pragma unroll
        for (int i = 0; i < 16; i++) {
            int idx = tid + i * 128;
            int r = idx >> 4, c = idx & 15;
            *(uint2*)&As[r * 72 + c * 4] =
                *(const uint2*)&g_h[(size_t)(m0 + r) * 512 + k0 + c * 4];
        }
        for (int idx = tid; idx < 40 * 64; idx += 128) {
            int k = idx & 63, n = idx >> 6;
            Bs[n * 72 + k] = (n < 37) ? __float2bfloat16(W2[(size_t)(k0 + k) * 37 + n])
                                      : __float2bfloat16(0.f);
        }
        __syncthreads();
#pragma unroll
        for (int kk = 0; kk < 64; kk += 16) {
            unsigned af[2][4], bfr[5][2];
#pragma unroll
            for (int i = 0; i < 2; i++) {
                int r = wrow + i * 16 + gp;
                af[i][0] = *(const unsigned*)&As[r * 72 + kk + tg * 2];
                af[i][1] = *(const unsigned*)&As[(r + 8) * 72 + kk + tg * 2];
                af[i][2] = *(const unsigned*)&As[r * 72 + kk + tg * 2 + 8];
                af[i][3] = *(const unsigned*)&As[(r + 8) * 72 + kk + tg * 2 + 8];
            }
#pragma unroll
            for (int j = 0; j < 5; j++) {
                int n = j * 8 + gp;
                bfr[j][0] = *(const unsigned*)&Bs[n * 72 + kk + tg * 2];
                bfr[j][1] = *(const unsigned*)&Bs[n * 72 + kk + tg * 2 + 8];
            }
#pragma unroll
            for (int i = 0; i < 2; i++)
#pragma unroll
                for (int j = 0; j < 5; j++) mma16816(acc[i][j], af[i], bfr[j]);
        }
    }

#pragma unroll
    for (int i = 0; i < 2; i++) {
        int r0 = m0 + wrow + i * 16 + gp;
        int r1 = r0 + 8;
#pragma unroll
        for (int j = 0; j < 5; j++) {
            int c = j * 8 + tg * 2;
            if (c < 37) {
                float bia = b2[c];
                g_expem[(size_t)r0 * 37 + c] = expf(acc[i][j][0] + bia);
                g_expem[(size_t)r1 * 37 + c] = expf(acc[i][j][2] + bia);
            }
            if (c + 1 < 37) {
                float bia = b2[c + 1];
                g_expem[(size_t)r0 * 37 + c + 1] = expf(acc[i][j][1] + bia);
                g_expem[(size_t)r1 * 37 + c + 1] = expf(acc[i][j][3] + bia);
            }
        }
    }
}

// ---------------- CRF: fwd/bwd split, 2 warps per recursion ----------------
// 160 threads: warps 0-1 forward (64 lanes, one output column each,
// bar.sync 1,64), warps 2-3 backward (bar.sync 2,64), warp 4 gold path.
// Per lane-step: 10 LDS.128 + 20 fma2 (vs 40 on one warp before).
__device__ __forceinline__ float col_step(const float* __restrict__ buf,
                                          const u64* __restrict__ EP, float em) {
    u64 A0 = 0ull, A1 = 0ull, A2 = 0ull, A3 = 0ull;
#pragma unroll
    for (int j = 0; j < 10; j++) {
        ulonglong2 v = *(const ulonglong2*)&buf[4 * j];   // LDS.128
        if (j & 1) { A2 = fma2(v.x, EP[2 * j], A2); A3 = fma2(v.y, EP[2 * j + 1], A3); }
        else       { A0 = fma2(v.x, EP[2 * j], A0); A1 = fma2(v.y, EP[2 * j + 1], A1); }
    }
    u64 st = add2(add2(A0, A2), add2(A1, A3));
    float lo, hi;
    unpack2(st, lo, hi);
    return (lo + hi) * em;
}

__global__ __launch_bounds__(160) void crf_kernel(const float* __restrict__ trans,
                                                  const float* __restrict__ startt,
                                                  const float* __restrict__ endt,
                                                  const int* __restrict__ labels,
                                                  const void* __restrict__ mask,
                                                  int b0) {
    __shared__ __align__(16) float sa[2][64];
    __shared__ __align__(16) float sb[2][64];
    __shared__ float gp_s, lsB_s;
    const int b = b0 + blockIdx.x, tid = threadIdx.x;
    const int lane = tid & 31;
    const unsigned FULL = 0xffffffffu;
    const size_t base = (size_t)b * 512;
    const int* lab = labels + base;

    // ---- per-warp length (mask dtype sniffed) ----
    int cnt = 0;
    const unsigned w0 = *(const unsigned*)mask;
    if (w0 == 0x01010101u) {
        const uint4* p = (const uint4*)((const unsigned char*)mask + base);
        uint4 v = p[lane];
        cnt = __popc(v.x & 0x01010101u) + __popc(v.y & 0x01010101u) +
              __popc(v.z & 0x01010101u) + __popc(v.w & 0x01010101u);
    } else if (w0 == 0x3F800000u) {
        const float* p = (const float*)mask + base;
        for (int i = lane; i < 512; i += 32) cnt += (p[i] != 0.f);
    } else {
        const int* p = (const int*)mask + base;
        for (int i = lane; i < 512; i += 32) cnt += (p[i] != 0);
    }
#pragma unroll
    for (int off = 16; off; off >>= 1) cnt += __shfl_xor_sync(FULL, cnt, off);
    const int len = cnt;
    const int mid = len >> 1;

    float logscaleF = 0.f;

    if (tid >= 128) {
        // ---- gold path (warp 4) ----
        float g = 0.f;
        for (int s = lane; s < len; s += 32)
            g += logf(g_expem[(base + s) * 37 + lab[s]]);
        for (int s = 1 + lane; s < len; s += 32)
            g += trans[lab[s - 1] * 37 + lab[s]];
        if (lane == 0) g += startt[lab[0]] + endt[lab[len - 1]];
#pragma unroll
        for (int off = 16; off; off >>= 1) g += __shfl_xor_sync(FULL, g, off);
        if (lane == 0) gp_s = g;
    } else if (tid < 64) {
        // ---- forward alpha: 64 lanes, col c = tid (active c<37) ----
        const int c = tid;
        const bool act = c < 37;
        const int cc = act ? c : 36;
        u64 EP[20];
#pragma unroll 1
        for (int i = 0; i < 20; i++) {
            int i0 = 2 * i, i1 = 2 * i + 1;
            float e0 = (act && i0 < 37) ? expf(trans[i0 * 37 + cc]) : 0.f;
            float e1 = (act && i1 < 37) ? expf(trans[i1 * 37 + cc]) : 0.f;
            EP[i] = pack2(e0, e1);
        }
        const float* emp = g_expem + base * 37 + cc;

        sa[0][c] = act ? expf(startt[c]) * emp[0] : 0.f;
        BAR_SYNC(1, 64);

        float cur[8], nxt[8];
#pragma unroll
        for (int u = 0; u < 8; u++) {
            cur[u] = emp[(1 + u) * 37];
            nxt[u] = emp[(9 + u) * 37];
        }

        const int Gf = mid >> 3;
        float na = 0.f;
        int s = 1;
#pragma unroll 1
        for (int g = 0; g < Gf; g++) {
#pragma unroll
            for (int u = 0; u < 8; u++) {
                const float* buf = sa[u & 1];
                na = col_step(buf, EP, cur[u]);
                if (u == 7) {
                    float scale = buf[0];
                    logscaleF += logf(scale);
                    na *= (1.f / scale);
                }
                sa[(u + 1) & 1][c] = na;
                BAR_SYNC(1, 64);
            }
            int sbase = s + 16;
#pragma unroll
            for (int u = 0; u < 8; u++) {
                cur[u] = nxt[u];
                int ss = sbase + u; ss = (ss < 512) ? ss : 511;
                nxt[u] = emp[ss * 37];
            }
            s += 8;
        }
#pragma unroll 1
        for (int u = 0; s <= mid; s++, u++) {
            const float* buf = sa[(s - 1) & 1];
            na = col_step(buf, EP, cur[u]);
            sa[s & 1][c] = na;
            BAR_SYNC(1, 64);
        }
    } else {
        // ---- backward g = em*beta: 64 lanes, col c = tid-64; uses E rows ----
        const int c = tid - 64;
        const bool act = c < 37;
        const int cc = act ? c : 36;
        u64 EP[20];
#pragma unroll 1
        for (int i = 0; i < 20; i++) {
            int i0 = 2 * i, i1 = 2 * i + 1;
            float e0 = (act && i0 < 37) ? expf(trans[cc * 37 + i0]) : 0.f;
            float e1 = (act && i1 < 37) ? expf(trans[cc * 37 + i1]) : 0.f;
            EP[i] = pack2(e0, e1);
        }
        const float* emp = g_expem + base * 37 + cc;

        sb[0][c] = act ? emp[(size_t)(len - 1) * 37] * expf(endt[c]) : 0.f;
        BAR_SYNC(2, 64);

        float cur[8], nxt[8];
#pragma unroll
        for (int u = 0; u < 8; u++) {
            cur[u] = emp[(len - 2 - u) * 37];
            nxt[u] = emp[(len - 10 - u) * 37];
        }

        const int V = len - 1 - mid;
        const int Gb = V >> 3;
        float na = 0.f;
        float logscaleB = 0.f;
        int nb = len - 18;
        int v = 0;
#pragma unroll 1
        for (int g = 0; g < Gb; g++) {
#pragma unroll
            for (int u = 0; u < 8; u++) {
                const float* buf = sb[u & 1];
                na = col_step(buf, EP, cur[u]);
                if (u == 7) {
                    float scale = buf[0];
                    logscaleB += logf(scale);
                    na *= (1.f / scale);
                }
                sb[(u + 1) & 1][c] = na;
                BAR_SYNC(2, 64);
            }
#pragma unroll
            for (int u = 0; u < 8; u++) {
                cur[u] = nxt[u];
                int ss = nb - u; ss = (ss > 0) ? ss : 0;
                nxt[u] = emp[ss * 37];
            }
            nb -= 8;
            v += 8;
        }
#pragma unroll 1
        for (int u = 0; v < V; v++, u++) {
            const float* buf = sb[v & 1];
            na = col_step(buf, EP, cur[u]);
            sb[(v + 1) & 1][c] = na;
            BAR_SYNC(2, 64);
        }
        if (c == 0) lsB_s = logscaleB;
    }
    __syncthreads();

    // ---- combine in warp0: Z = sum alpha_mid * g_mid / em_mid ----
    if (tid < 32) {
        const int t = lane;
        const bool hi = (t < 5);
        const int V = len - 1 - mid;
        const float* am = sa[mid & 1];
        const float* gm = sb[V & 1];
        float emLm = g_expem[(base + mid) * 37 + t];
        float emHm = hi ? g_expem[(base + mid) * 37 + t + 32] : 1.f;
        float z = am[t] * gm[t] / emLm + (hi ? am[t + 32] * gm[t + 32] / emHm : 0.f);
#pragma unroll
        for (int off = 16; off; off >>= 1) z += __shfl_xor_sync(FULL, z, off);
        if (t == 0) g_partial[b] = logscaleF + lsB_s + logf(z) - gp_s;
    }
}

// ---------------- finalize: mean over batches ----------------
__global__ void finalize_kernel(float* __restrict__ out) {
    const int t = threadIdx.x;
    float v = g_partial[t] + g_partial[t + 32];
#pragma unroll
    for (int off = 16; off; off >>= 1) v += __shfl_xor_sync(0xffffffffu, v, off);
    if (t == 0) out[0] = v * (1.f / 64.f);
}

// ---------------- launch: 2-chunk pipeline (128/128, as in R12) ----------------
extern "C" void kernel_launch(void* const* d_in, const int* in_sizes, int n_in,
                              void* d_out, int out_size) {
    const float* X      = (const float*)d_in[0];
    const void*  mask   = d_in[1];
    const int*   labels = (const int*)d_in[2];
    const float* W1     = (const float*)d_in[3];
    const float* b1     = (const float*)d_in[4];
    const float* W2     = (const float*)d_in[5];
    const float* b2     = (const float*)d_in[6];
    const float* trans  = (const float*)d_in[7];
    const float* startt = (const float*)d_in[8];
    const float* endt   = (const float*)d_in[9];
    float* out = (float*)d_out;

    static cudaStream_t s1 = nullptr;
    static cudaEvent_t evA = nullptr, evB = nullptr;
    if (!s1) {
        cudaFuncSetAttribute(gemm1_kernel,
                             cudaFuncAttributeMaxDynamicSharedMemorySize, G1_SMEM);
        cudaStreamCreateWithFlags(&s1, cudaStreamNonBlocking);
        cudaEventCreateWithFlags(&evA, cudaEventDisableTiming);
        cudaEventCreateWithFlags(&evB, cudaEventDisableTiming);
    }

    gemm1_kernel<<<128, 256, G1_SMEM>>>(X, W1, b1, 0);
    cudaEventRecord(evA, 0);
    gemm1_kernel<<<128, 256, G1_SMEM>>>(X, W1, b1, 128);   // default stream

    cudaStreamWaitEvent(s1, evA, 0);
    gemm2_kernel<<<128, 128, 0, s1>>>(W2, b2, 0);
    crf_kernel<<<32, 160, 0, s1>>>(trans, startt, endt, labels, mask, 0);
    cudaEventRecord(evB, s1);

    gemm2_kernel<<<128, 128>>>(W2, b2, 128);
    crf_kernel<<<32, 160>>>(trans, startt, endt, labels, mask, 32);
    cudaStreamWaitEvent(0, evB, 0);
    finalize_kernel<<<1, 32>>>(out);
}

// round 15
// speedup vs baseline: 1.1942x; 1.1698x over previous
#include <cuda_runtime.h>
#include <cuda_bf16.h>
#include <cstdint>
#include <cstddef>

// Shapes: B=64, S=512, D=768, H=512, T=37. Output: scalar f32 loss.

// ---------------- device scratch (no runtime allocation) ----------------
__device__ __align__(16) __nv_bfloat16 g_h[(size_t)32768 * 512];   // 32 MB hidden
__device__ __align__(16) float g_expem[(size_t)32768 * 37];        // exp(logits)
__device__ float g_partial[64];

typedef unsigned long long u64;

// ---------------- helpers ----------------
__device__ __forceinline__ void mma16816(float* d, const unsigned* a, const unsigned* b) {
    asm volatile(
        "mma.sync.aligned.m16n8k16.row.col.f32.bf16.bf16.f32 "
        "{%0,%1,%2,%3},{%4,%5,%6,%7},{%8,%9},{%0,%1,%2,%3};\n"
        : "+f"(d[0]), "+f"(d[1]), "+f"(d[2]), "+f"(d[3])
        : "r"(a[0]), "r"(a[1]), "r"(a[2]), "r"(a[3]), "r"(b[0]), "r"(b[1]));
}

__device__ __forceinline__ void ldsm_x4(unsigned& r0, unsigned& r1, unsigned& r2,
                                        unsigned& r3, uint32_t addr) {
    asm volatile("ldmatrix.sync.aligned.m8n8.x4.shared.b16 {%0,%1,%2,%3}, [%4];"
                 : "=r"(r0), "=r"(r1), "=r"(r2), "=r"(r3) : "r"(addr));
}

__device__ __forceinline__ uint32_t smem_u32(const void* p) {
    uint32_t a;
    asm("{ .reg .u64 t; cvta.to.shared.u64 t, %1; cvt.u32.u64 %0, t; }" : "=r"(a) : "l"(p));
    return a;
}

__device__ __forceinline__ uint2 pack_bf16x4(float a, float b, float c, float d) {
    __nv_bfloat162 h0 = __floats2bfloat162_rn(a, b);
    __nv_bfloat162 h1 = __floats2bfloat162_rn(c, d);
    uint2 r;
    r.x = *reinterpret_cast<unsigned*>(&h0);
    r.y = *reinterpret_cast<unsigned*>(&h1);
    return r;
}

__device__ __forceinline__ u64 pack2(float lo, float hi) {
    u64 v; asm("mov.b64 %0, {%1, %2};" : "=l"(v) : "f"(lo), "f"(hi)); return v;
}
__device__ __forceinline__ void unpack2(u64 v, float& lo, float& hi) {
    asm("mov.b64 {%0, %1}, %2;" : "=f"(lo), "=f"(hi) : "l"(v));
}
__device__ __forceinline__ u64 fma2(u64 a, u64 b, u64 c) {
    u64 d; asm("fma.rn.f32x2 %0, %1, %2, %3;" : "=l"(d) : "l"(a), "l"(b), "l"(c)); return d;
}
__device__ __forceinline__ u64 add2(u64 a, u64 b) {
    u64 d; asm("add.rn.f32x2 %0, %1, %2;" : "=l"(d) : "l"(a), "l"(b)); return d;
}
#define BAR_SYNC(id, cnt) \
    asm volatile("bar.sync %0, %1;" :: "r"(id), "r"(cnt) : "memory")

// ---------------- GEMM1: h = relu(X@W1 + b1) ----------------
// 128x128 tiles, BK=32, double-buffered 40KB static smem,
// __launch_bounds__(256,2) -> 2 blocks/SM (16 warps) for issue hiding.
// Grid (4 n-tiles, m-tiles). LDSM stride 40 -> conflict-free fragment reads.
#define G1_STRIDE 40
#define G1_TILE   (128 * G1_STRIDE)
__global__ __launch_bounds__(256, 2) void gemm1_kernel(const float* __restrict__ X,
                                                       const float* __restrict__ W1,
                                                       const float* __restrict__ b1,
                                                       int mtile0) {
    __shared__ __nv_bfloat16 As[2][G1_TILE];
    __shared__ __nv_bfloat16 Bs[2][G1_TILE];
    const int tid  = threadIdx.x;
    const int lane = tid & 31;
    const int wid  = tid >> 5;
    const int wm   = wid & 3;
    const int wn   = wid >> 2;
    const int m0   = (mtile0 + blockIdx.y) * 128;
    const int n0   = blockIdx.x * 128;
    const int wrow = wm * 32;
    const int wcol = wn * 64;
    const int gp   = lane >> 2;
    const int tg   = lane & 3;
    const int nc   = tid & 127;
    const int kgb  = (tid >> 7) * 4;

    const uint32_t as_u32 = smem_u32(As);
    const uint32_t bs_u32 = smem_u32(Bs);
    const int rowA  = wrow + (lane & 7) + ((lane >> 3) & 1) * 8;
    const int kaddA = ((lane >> 4) & 1) * 8;
    const uint32_t aoff = (uint32_t)(rowA * G1_STRIDE + kaddA) * 2;
    const int rowB  = wcol + (lane & 7) + ((lane >> 4) & 1) * 8;
    const int kaddB = ((lane >> 3) & 1) * 8;
    const uint32_t boff = (uint32_t)(rowB * G1_STRIDE + kaddB) * 2;

    float acc[2][8][4];
#pragma unroll
    for (int i = 0; i < 2; i++)
#pragma unroll
        for (int j = 0; j < 8; j++)
#pragma unroll
            for (int k = 0; k < 4; k++) acc[i][j][k] = 0.f;

    float4 ra[4];
    float rb[4][4];
    const int rA = tid >> 3;           // A staging row (0..127... wait 256 threads /8 = 32)
    // A staging: idx = tid + i*256; r = idx>>3, c = idx&7 (float4 col)

    // ---- load + stage kt=0 ----
#pragma unroll
    for (int i = 0; i < 4; i++) {
        int idx = tid + i * 256;
        int r = idx >> 3, c = idx & 7;
        ra[i] = *(const float4*)(X + (size_t)(m0 + r) * 768 + c * 4);
    }
#pragma unroll
    for (int i = 0; i < 4; i++) {
        int kr = kgb + i * 8;
#pragma unroll
        for (int j = 0; j < 4; j++)
            rb[i][j] = W1[(size_t)(kr + j) * 512 + n0 + nc];
    }
#pragma unroll
    for (int i = 0; i < 4; i++) {
        int idx = tid + i * 256;
        int r = idx >> 3, c = idx & 7;
        *(uint2*)&As[0][r * G1_STRIDE + c * 4] =
            pack_bf16x4(ra[i].x, ra[i].y, ra[i].z, ra[i].w);
    }
#pragma unroll
    for (int i = 0; i < 4; i++) {
        int kr = kgb + i * 8;
        *(uint2*)&Bs[0][nc * G1_STRIDE + kr] =
            pack_bf16x4(rb[i][0], rb[i][1], rb[i][2], rb[i][3]);
    }
    // ---- load kt=1 ----
#pragma unroll
    for (int i = 0; i < 4; i++) {
        int idx = tid + i * 256;
        int r = idx >> 3, c = idx & 7;
        ra[i] = *(const float4*)(X + (size_t)(m0 + r) * 768 + 32 + c * 4);
    }
#pragma unroll
    for (int i = 0; i < 4; i++) {
        int kr = 32 + kgb + i * 8;
#pragma unroll
        for (int j = 0; j < 4; j++)
            rb[i][j] = W1[(size_t)(kr + j) * 512 + n0 + nc];
    }
    __syncthreads();

    for (int kt = 0; kt < 24; kt++) {
        if (kt < 23) {
            const int st = (kt + 1) & 1;
#pragma unroll
            for (int i = 0; i < 4; i++) {
                int idx = tid + i * 256;
                int r = idx >> 3, c = idx & 7;
                *(uint2*)&As[st][r * G1_STRIDE + c * 4] =
                    pack_bf16x4(ra[i].x, ra[i].y, ra[i].z, ra[i].w);
            }
#pragma unroll
            for (int i = 0; i < 4; i++) {
                int kr = kgb + i * 8;
                *(uint2*)&Bs[st][nc * G1_STRIDE + kr] =
                    pack_bf16x4(rb[i][0], rb[i][1], rb[i][2], rb[i][3]);
            }
        }
        if (kt < 22) {
            int k0 = (kt + 2) * 32;
#pragma unroll
            for (int i = 0; i < 4; i++) {
                int idx = tid + i * 256;
                int r = idx >> 3, c = idx & 7;
                ra[i] = *(const float4*)(X + (size_t)(m0 + r) * 768 + k0 + c * 4);
            }
#pragma unroll
            for (int i = 0; i < 4; i++) {
                int kr = k0 + kgb + i * 8;
#pragma unroll
                for (int j = 0; j < 4; j++)
                    rb[i][j] = W1[(size_t)(kr + j) * 512 + n0 + nc];
            }
        }
        // MMA from buffer kt&1
        const uint32_t ab = as_u32 + (uint32_t)((kt & 1) * G1_TILE * 2) + aoff;
        const uint32_t bb = bs_u32 + (uint32_t)((kt & 1) * G1_TILE * 2) + boff;
#pragma unroll
        for (int kk = 0; kk < 32; kk += 16) {
            const uint32_t k2 = (uint32_t)kk * 2;
            unsigned af[2][4], bfr[8][2];
            ldsm_x4(af[0][0], af[0][1], af[0][2], af[0][3], ab + k2);
            ldsm_x4(af[1][0], af[1][1], af[1][2], af[1][3],
                    ab + 16 * G1_STRIDE * 2 + k2);
#pragma unroll
            for (int j2 = 0; j2 < 4; j2++)
                ldsm_x4(bfr[2 * j2][0], bfr[2 * j2][1],
                        bfr[2 * j2 + 1][0], bfr[2 * j2 + 1][1],
                        bb + (uint32_t)(j2 * 16 * G1_STRIDE) * 2 + k2);
#pragma unroll
            for (int i = 0; i < 2; i++)
#pragma unroll
                for (int j = 0; j < 8; j++) mma16816(acc[i][j], af[i], bfr[j]);
        }
        __syncthreads();
    }

    // epilogue: bias + relu, store bf16
#pragma unroll
    for (int i = 0; i < 2; i++) {
        int r0 = m0 + wrow + i * 16 + gp;
        int r1 = r0 + 8;
#pragma unroll
        for (int j = 0; j < 8; j++) {
            int c = n0 + wcol + j * 8 + tg * 2;
            float bia0 = b1[c], bia1 = b1[c + 1];
            float v00 = fmaxf(acc[i][j][0] + bia0, 0.f);
            float v01 = fmaxf(acc[i][j][1] + bia1, 0.f);
            float v10 = fmaxf(acc[i][j][2] + bia0, 0.f);
            float v11 = fmaxf(acc[i][j][3] + bia1, 0.f);
            __nv_bfloat162 o0 = __floats2bfloat162_rn(v00, v01);
            __nv_bfloat162 o1 = __floats2bfloat162_rn(v10, v11);
            *(__nv_bfloat162*)&g_h[(size_t)r0 * 512 + c] = o0;
            *(__nv_bfloat162*)&g_h[(size_t)r1 * 512 + c] = o1;
        }
    }
}

// ---------------- GEMM2: expem = exp(h@W2 + b2) ----------------
__global__ __launch_bounds__(128) void gemm2_kernel(const float* __restrict__ W2,
                                                    const float* __restrict__ b2,
                                                    int mtile0) {
    __shared__ __nv_bfloat16 As[128 * 72];
    __shared__ __nv_bfloat16 Bs[40 * 72];
    const int tid  = threadIdx.x;
    const int lane = tid & 31;
    const int wid  = tid >> 5;
    const int m0   = (mtile0 + blockIdx.x) * 128;
    const int wrow = wid * 32;
    const int gp   = lane >> 2;
    const int tg   = lane & 3;

    float acc[2][5][4];
#pragma unroll
    for (int i = 0; i < 2; i++)
#pragma unroll
        for (int j = 0; j < 5; j++)
#pragma unroll
            for (int k = 0; k < 4; k++) acc[i][j][k] = 0.f;

    for (int kt = 0; kt < 8; kt++) {
        __syncthreads();
        int k0 = kt * 64;
#pragma unroll
        for (int i = 0; i < 16; i++) {
            int idx = tid + i * 128;
            int r = idx >> 4, c = idx & 15;
            *(uint2*)&As[r * 72 + c * 4] =
                *(const uint2*)&g_h[(size_t)(m0 + r) * 512 + k0 + c * 4];
        }
        for (int idx = tid; idx < 40 * 64; idx += 128) {
            int k = idx & 63, n = idx >> 6;
            Bs[n * 72 + k] = (n < 37) ? __float2bfloat16(W2[(size_t)(k0 + k) * 37 + n])
                                      : __float2bfloat16(0.f);
        }
        __syncthreads();
#pragma unroll
        for (int kk = 0; kk < 64; kk += 16) {
            unsigned af[2][4], bfr[5][2];
#pragma unroll
            for (int i = 0; i < 2; i++) {
                int r = wrow + i * 16 + gp;
                af[i][0] = *(const unsigned*)&As[r * 72 + kk + tg * 2];
                af[i][1] = *(const unsigned*)&As[(r + 8) * 72 + kk + tg * 2];
                af[i][2] = *(const unsigned*)&As[r * 72 + kk + tg * 2 + 8];
                af[i][3] = *(const unsigned*)&As[(r + 8) * 72 + kk + tg * 2 + 8];
            }
#pragma unroll
            for (int j = 0; j < 5; j++) {
                int n = j * 8 + gp;
                bfr[j][0] = *(const unsigned*)&Bs[n * 72 + kk + tg * 2];
                bfr[j][1] = *(const unsigned*)&Bs[n * 72 + kk + tg * 2 + 8];
            }
#pragma unroll
            for (int i = 0; i < 2; i++)
#pragma unroll
                for (int j = 0; j < 5; j++) mma16816(acc[i][j], af[i], bfr[j]);
        }
    }

#pragma unroll
    for (int i = 0; i < 2; i++) {
        int r0 = m0 + wrow + i * 16 + gp;
        int r1 = r0 + 8;
#pragma unroll
        for (int j = 0; j < 5; j++) {
            int c = j * 8 + tg * 2;
            if (c < 37) {
                float bia = b2[c];
                g_expem[(size_t)r0 * 37 + c] = expf(acc[i][j][0] + bia);
                g_expem[(size_t)r1 * 37 + c] = expf(acc[i][j][2] + bia);
            }
            if (c + 1 < 37) {
                float bia = b2[c + 1];
                g_expem[(size_t)r0 * 37 + c + 1] = expf(acc[i][j][1] + bia);
                g_expem[(size_t)r1 * 37 + c + 1] = expf(acc[i][j][3] + bia);
            }
        }
    }
}

// ---------------- CRF: fwd/bwd split, 2 warps per recursion (R14) ----------------
__device__ __forceinline__ float col_step(const float* __restrict__ buf,
                                          const u64* __restrict__ EP, float em) {
    u64 A0 = 0ull, A1 = 0ull, A2 = 0ull, A3 = 0ull;
#pragma unroll
    for (int j = 0; j < 10; j++) {
        ulonglong2 v = *(const ulonglong2*)&buf[4 * j];   // LDS.128
        if (j & 1) { A2 = fma2(v.x, EP[2 * j], A2); A3 = fma2(v.y, EP[2 * j + 1], A3); }
        else       { A0 = fma2(v.x, EP[2 * j], A0); A1 = fma2(v.y, EP[2 * j + 1], A1); }
    }
    u64 st = add2(add2(A0, A2), add2(A1, A3));
    float lo, hi;
    unpack2(st, lo, hi);
    return (lo + hi) * em;
}

__global__ __launch_bounds__(160) void crf_kernel(const float* __restrict__ trans,
                                                  const float* __restrict__ startt,
                                                  const float* __restrict__ endt,
                                                  const int* __restrict__ labels,
                                                  const void* __restrict__ mask,
                                                  int b0) {
    __shared__ __align__(16) float sa[2][64];
    __shared__ __align__(16) float sb[2][64];
    __shared__ float gp_s, lsB_s;
    const int b = b0 + blockIdx.x, tid = threadIdx.x;
    const int lane = tid & 31;
    const unsigned FULL = 0xffffffffu;
    const size_t base = (size_t)b * 512;
    const int* lab = labels + base;

    int cnt = 0;
    const unsigned w0 = *(const unsigned*)mask;
    if (w0 == 0x01010101u) {
        const uint4* p = (const uint4*)((const unsigned char*)mask + base);
        uint4 v = p[lane];
        cnt = __popc(v.x & 0x01010101u) + __popc(v.y & 0x01010101u) +
              __popc(v.z & 0x01010101u) + __popc(v.w & 0x01010101u);
    } else if (w0 == 0x3F800000u) {
        const float* p = (const float*)mask + base;
        for (int i = lane; i < 512; i += 32) cnt += (p[i] != 0.f);
    } else {
        const int* p = (const int*)mask + base;
        for (int i = lane; i < 512; i += 32) cnt += (p[i] != 0);
    }
#pragma unroll
    for (int off = 16; off; off >>= 1) cnt += __shfl_xor_sync(FULL, cnt, off);
    const int len = cnt;
    const int mid = len >> 1;

    float logscaleF = 0.f;

    if (tid >= 128) {
        float g = 0.f;
        for (int s = lane; s < len; s += 32)
            g += logf(g_expem[(base + s) * 37 + lab[s]]);
        for (int s = 1 + lane; s < len; s += 32)
            g += trans[lab[s - 1] * 37 + lab[s]];
        if (lane == 0) g += startt[lab[0]] + endt[lab[len - 1]];
#pragma unroll
        for (int off = 16; off; off >>= 1) g += __shfl_xor_sync(FULL, g, off);
        if (lane == 0) gp_s = g;
    } else if (tid < 64) {
        const int c = tid;
        const bool act = c < 37;
        const int cc = act ? c : 36;
        u64 EP[20];
#pragma unroll 1
        for (int i = 0; i < 20; i++) {
            int i0 = 2 * i, i1 = 2 * i + 1;
            float e0 = (act && i0 < 37) ? expf(trans[i0 * 37 + cc]) : 0.f;
            float e1 = (act && i1 < 37) ? expf(trans[i1 * 37 + cc]) : 0.f;
            EP[i] = pack2(e0, e1);
        }
        const float* emp = g_expem + base * 37 + cc;

        sa[0][c] = act ? expf(startt[c]) * emp[0] : 0.f;
        BAR_SYNC(1, 64);

        float cur[8], nxt[8];
#pragma unroll
        for (int u = 0; u < 8; u++) {
            cur[u] = emp[(1 + u) * 37];
            nxt[u] = emp[(9 + u) * 37];
        }

        const int Gf = mid >> 3;
        float na = 0.f;
        int s = 1;
#pragma unroll 1
        for (int g = 0; g < Gf; g++) {
#pragma unroll
            for (int u = 0; u < 8; u++) {
                const float* buf = sa[u & 1];
                na = col_step(buf, EP, cur[u]);
                if (u == 7) {
                    float scale = buf[0];
                    logscaleF += logf(scale);
                    na *= (1.f / scale);
                }
                sa[(u + 1) & 1][c] = na;
                BAR_SYNC(1, 64);
            }
            int sbase = s + 16;
#pragma unroll
            for (int u = 0; u < 8; u++) {
                cur[u] = nxt[u];
                int ss = sbase + u; ss = (ss < 512) ? ss : 511;
                nxt[u] = emp[ss * 37];
            }
            s += 8;
        }
#pragma unroll 1
        for (int u = 0; s <= mid; s++, u++) {
            const float* buf = sa[(s - 1) & 1];
            na = col_step(buf, EP, cur[u]);
            sa[s & 1][c] = na;
            BAR_SYNC(1, 64);
        }
    } else {
        const int c = tid - 64;
        const bool act = c < 37;
        const int cc = act ? c : 36;
        u64 EP[20];
#pragma unroll 1
        for (int i = 0; i < 20; i++) {
            int i0 = 2 * i, i1 = 2 * i + 1;
            float e0 = (act && i0 < 37) ? expf(trans[cc * 37 + i0]) : 0.f;
            float e1 = (act && i1 < 37) ? expf(trans[cc * 37 + i1]) : 0.f;
            EP[i] = pack2(e0, e1);
        }
        const float* emp = g_expem + base * 37 + cc;

        sb[0][c] = act ? emp[(size_t)(len - 1) * 37] * expf(endt[c]) : 0.f;
        BAR_SYNC(2, 64);

        float cur[8], nxt[8];
#pragma unroll
        for (int u = 0; u < 8; u++) {
            cur[u] = emp[(len - 2 - u) * 37];
            nxt[u] = emp[(len - 10 - u) * 37];
        }

        const int V = len - 1 - mid;
        const int Gb = V >> 3;
        float na = 0.f;
        float logscaleB = 0.f;
        int nb = len - 18;
        int v = 0;
#pragma unroll 1
        for (int g = 0; g < Gb; g++) {
#pragma unroll
            for (int u = 0; u < 8; u++) {
                const float* buf = sb[u & 1];
                na = col_step(buf, EP, cur[u]);
                if (u == 7) {
                    float scale = buf[0];
                    logscaleB += logf(scale);
                    na *= (1.f / scale);
                }
                sb[(u + 1) & 1][c] = na;
                BAR_SYNC(2, 64);
            }
#pragma unroll
            for (int u = 0; u < 8; u++) {
                cur[u] = nxt[u];
                int ss = nb - u; ss = (ss > 0) ? ss : 0;
                nxt[u] = emp[ss * 37];
            }
            nb -= 8;
            v += 8;
        }
#pragma unroll 1
        for (int u = 0; v < V; v++, u++) {
            const float* buf = sb[v & 1];
            na = col_step(buf, EP, cur[u]);
            sb[(v + 1) & 1][c] = na;
            BAR_SYNC(2, 64);
        }
        if (c == 0) lsB_s = logscaleB;
    }
    __syncthreads();

    if (tid < 32) {
        const int t = lane;
        const bool hi = (t < 5);
        const int V = len - 1 - mid;
        const float* am = sa[mid & 1];
        const float* gm = sb[V & 1];
        float emLm = g_expem[(base + mid) * 37 + t];
        float emHm = hi ? g_expem[(base + mid) * 37 + t + 32] : 1.f;
        float z = am[t] * gm[t] / emLm + (hi ? am[t + 32] * gm[t + 32] / emHm : 0.f);
#pragma unroll
        for (int off = 16; off; off >>= 1) z += __shfl_xor_sync(FULL, z, off);
        if (t == 0) g_partial[b] = logscaleF + lsB_s + logf(z) - gp_s;
    }
}

// ---------------- finalize: mean over batches ----------------
__global__ void finalize_kernel(float* __restrict__ out) {
    const int t = threadIdx.x;
    float v = g_partial[t] + g_partial[t + 32];
#pragma unroll
    for (int off = 16; off; off >>= 1) v += __shfl_xor_sync(0xffffffffu, v, off);
    if (t == 0) out[0] = v * (1.f / 64.f);
}

// ---------------- launch: 2-chunk pipeline (128/128) ----------------
extern "C" void kernel_launch(void* const* d_in, const int* in_sizes, int n_in,
                              void* d_out, int out_size) {
    const float* X      = (const float*)d_in[0];
    const void*  mask   = d_in[1];
    const int*   labels = (const int*)d_in[2];
    const float* W1     = (const float*)d_in[3];
    const float* b1     = (const float*)d_in[4];
    const float* W2     = (const float*)d_in[5];
    const float* b2     = (const float*)d_in[6];
    const float* trans  = (const float*)d_in[7];
    const float* startt = (const float*)d_in[8];
    const float* endt   = (const float*)d_in[9];
    float* out = (float*)d_out;

    static cudaStream_t s1 = nullptr;
    static cudaEvent_t evA = nullptr, evB = nullptr;
    if (!s1) {
        cudaStreamCreateWithFlags(&s1, cudaStreamNonBlocking);
        cudaEventCreateWithFlags(&evA, cudaEventDisableTiming);
        cudaEventCreateWithFlags(&evB, cudaEventDisableTiming);
    }

    gemm1_kernel<<<dim3(4, 128), 256>>>(X, W1, b1, 0);
    cudaEventRecord(evA, 0);
    gemm1_kernel<<<dim3(4, 128), 256>>>(X, W1, b1, 128);   // default stream

    cudaStreamWaitEvent(s1, evA, 0);
    gemm2_kernel<<<128, 128, 0, s1>>>(W2, b2, 0);
    crf_kernel<<<32, 160, 0, s1>>>(trans, startt, endt, labels, mask, 0);
    cudaEventRecord(evB, s1);

    gemm2_kernel<<<128, 128>>>(W2, b2, 128);
    crf_kernel<<<32, 160>>>(trans, startt, endt, labels, mask, 32);
    cudaStreamWaitEvent(0, evB, 0);
    finalize_kernel<<<1, 32>>>(out);
}